// round 11
// baseline (speedup 1.0000x reference)
#include <cuda_runtime.h>
#include <cstdint>

constexpr int N_NODES = 50000;
constexpr int N_EDGES = 800000;
constexpr int CAP     = 96;      // per-dst bucket capacity (deg ~ Poisson(16), max ~50)
constexpr int NPAD    = 50176;   // padded node count (tiles touch full 128-row tiles)
constexpr int NB      = (N_NODES + 127) / 128;   // 391 tiles

// Scratch (static device globals — no allocs). Reused across layers.
__device__ float    g_t[(size_t)NPAD * 128];      // t1 / t2 / t3 (t3 uses 64-wide rows)
__device__ uint32_t g_xhi[(size_t)NPAD * 64];     // activated X, bf16 hi plane (interleaved k2 words)
__device__ uint32_t g_xlo[(size_t)NPAD * 64];     // activated X, bf16 lo plane
__device__ int      g_cursor[N_NODES];
__device__ int      g_slots[(size_t)N_NODES * CAP];
__device__ __align__(16) uint2 g_Wpre2[21248];    // pre-split bf16 hi/lo W, pair-packed

// uint2 offsets into g_Wpre2  (layer1/2: [32][132], layer3: [32][68])
constexpr int L1HI = 0,     L1LO = 4224;
constexpr int L2HI = 8448,  L2LO = 12672;
constexpr int L3HI = 16896, L3LO = 19072;

// ---------------- helpers ----------------
__device__ __forceinline__ uint32_t cvt2(float lo, float hi) {
    uint32_t r;
    asm("cvt.rn.bf16x2.f32 %0, %1, %2;" : "=r"(r) : "f"(hi), "f"(lo));
    return r;
}
__device__ __forceinline__ float unlo(uint32_t w) { return __uint_as_float(w << 16); }
__device__ __forceinline__ float unhi(uint32_t w) { return __uint_as_float(w & 0xFFFF0000u); }

#define MMA_BF16(c, a0, a1, a2, a3, b0, b1)                                      \
    asm volatile(                                                                \
        "mma.sync.aligned.m16n8k16.row.col.f32.bf16.bf16.f32 "                   \
        "{%0,%1,%2,%3},{%4,%5,%6,%7},{%8,%9},{%0,%1,%2,%3};"                     \
        : "+f"(c[0]), "+f"(c[1]), "+f"(c[2]), "+f"(c[3])                         \
        : "r"(a0), "r"(a1), "r"(a2), "r"(a3), "r"(b0), "r"(b1))

// ---------------------------------------------------------------------------
// Combined build: blocks [0, FB) fill CSR buckets; blocks [FB, FB+3) pre-split W
// into pair-packed uint2 tiles: B2[(kc*4+q)][n] = (w(k2=kc*8+q), w(k2+4)).
// ---------------------------------------------------------------------------
constexpr int FB = (N_EDGES + 255) / 256;    // 3125

__global__ void build_kernel(const int* __restrict__ src, const int* __restrict__ dst,
                             const float* __restrict__ W1, const float* __restrict__ W2,
                             const float* __restrict__ W3)
{
    if (blockIdx.x < FB) {
        int e = blockIdx.x * 256 + threadIdx.x;
        if (e >= N_EDGES) return;
        int d = dst[e];
        int p = atomicAdd(&g_cursor[d], 1);
        if (p < CAP) g_slots[(size_t)d * CAP + p] = src[e];
        return;
    }
    const int layer = blockIdx.x - FB;
    const float* W = (layer == 0) ? W1 : (layer == 1) ? W2 : W3;
    const int NO  = (layer == 2) ? 64 : 128;
    const int WP2 = (layer == 2) ? 68 : 132;
    uint2* hi = g_Wpre2 + ((layer == 0) ? L1HI : (layer == 1) ? L2HI : L3HI);
    uint2* lo = g_Wpre2 + ((layer == 0) ? L1LO : (layer == 1) ? L2LO : L3LO);

    for (int i = threadIdx.x; i < 32 * NO; i += 256) {
        int row = i / NO;                 // kc*4 + q
        int n   = i - row * NO;
        int kc = row >> 2, q = row & 3;
        int k2a = kc * 8 + q;
        float2 wa = *(const float2*)&W[n * 128 + 2 * k2a];
        float2 wb = *(const float2*)&W[n * 128 + 2 * (k2a + 4)];
        uint32_t ha = cvt2(wa.x, wa.y), hb = cvt2(wb.x, wb.y);
        uint32_t la = cvt2(wa.x - unlo(ha), wa.y - unhi(ha));
        uint32_t lb = cvt2(wb.x - unlo(hb), wb.y - unhi(hb));
        hi[row * WP2 + n] = make_uint2(ha, hb);
        lo[row * WP2 + n] = make_uint2(la, lb);
    }
}

// ---------------------------------------------------------------------------
// Fused gather+activate+pack (LTS-cap shape, warp per node):
//   X[n,:] = pack_bf16_hilo( relu( t[n,:] + sum_bucket(n) t[s,:] + b ) )
// Words stored in pair-interleaved order: within each 8-word group,
// original (q, q+4) sit at positions (2q, 2q+1).
// ---------------------------------------------------------------------------
__global__ void gatherx_kernel(const float* __restrict__ t,
                               const float* __restrict__ b,
                               uint32_t* __restrict__ Xhi,
                               uint32_t* __restrict__ Xlo)
{
    int node = blockIdx.x * 8 + (threadIdx.x >> 5);
    if (node >= N_NODES) return;
    int l = threadIdx.x & 31;
    int deg = g_cursor[node];
    if (deg > CAP) deg = CAP;
    const int* sl = &g_slots[(size_t)node * CAP];
    const float* tb = t + 4 * l;

    float4 acc = make_float4(0.f, 0.f, 0.f, 0.f);
    int j = 0;
    for (; j + 7 < deg; j += 8) {
        float4 v0 = *(const float4*)&tb[(size_t)sl[j    ] * 128];
        float4 v1 = *(const float4*)&tb[(size_t)sl[j + 1] * 128];
        float4 v2 = *(const float4*)&tb[(size_t)sl[j + 2] * 128];
        float4 v3 = *(const float4*)&tb[(size_t)sl[j + 3] * 128];
        float4 v4 = *(const float4*)&tb[(size_t)sl[j + 4] * 128];
        float4 v5 = *(const float4*)&tb[(size_t)sl[j + 5] * 128];
        float4 v6 = *(const float4*)&tb[(size_t)sl[j + 6] * 128];
        float4 v7 = *(const float4*)&tb[(size_t)sl[j + 7] * 128];
        acc.x += (v0.x + v1.x) + (v2.x + v3.x) + (v4.x + v5.x) + (v6.x + v7.x);
        acc.y += (v0.y + v1.y) + (v2.y + v3.y) + (v4.y + v5.y) + (v6.y + v7.y);
        acc.z += (v0.z + v1.z) + (v2.z + v3.z) + (v4.z + v5.z) + (v6.z + v7.z);
        acc.w += (v0.w + v1.w) + (v2.w + v3.w) + (v4.w + v5.w) + (v6.w + v7.w);
    }
    for (; j + 3 < deg; j += 4) {
        float4 v0 = *(const float4*)&tb[(size_t)sl[j    ] * 128];
        float4 v1 = *(const float4*)&tb[(size_t)sl[j + 1] * 128];
        float4 v2 = *(const float4*)&tb[(size_t)sl[j + 2] * 128];
        float4 v3 = *(const float4*)&tb[(size_t)sl[j + 3] * 128];
        acc.x += (v0.x + v1.x) + (v2.x + v3.x);
        acc.y += (v0.y + v1.y) + (v2.y + v3.y);
        acc.z += (v0.z + v1.z) + (v2.z + v3.z);
        acc.w += (v0.w + v1.w) + (v2.w + v3.w);
    }
    for (; j < deg; j++) {
        float4 v = *(const float4*)&tb[(size_t)sl[j] * 128];
        acc.x += v.x; acc.y += v.y; acc.z += v.z; acc.w += v.w;
    }

    float4 tv = *(const float4*)&t[(size_t)node * 128 + 4 * l];
    float4 bv = *(const float4*)&b[4 * l];
    float4 xv;
    xv.x = fmaxf(tv.x + acc.x + bv.x, 0.f);
    xv.y = fmaxf(tv.y + acc.y + bv.y, 0.f);
    xv.z = fmaxf(tv.z + acc.z + bv.z, 0.f);
    xv.w = fmaxf(tv.w + acc.w + bv.w, 0.f);

    uint32_t h0 = cvt2(xv.x, xv.y), h1 = cvt2(xv.z, xv.w);
    uint32_t l0 = cvt2(xv.x - unlo(h0), xv.y - unhi(h0));
    uint32_t l1 = cvt2(xv.z - unlo(h1), xv.w - unhi(h1));

    // interleaved positions: orig words (2m, 2m+1), m = l&3, group base 8*(l>>2)
    int m = l & 3;
    int p0 = 8 * (l >> 2) + 4 * (m & 1) + (m >> 1);
    size_t base = (size_t)node * 64;
    Xhi[base + p0]     = h0;
    Xhi[base + p0 + 2] = h1;
    Xlo[base + p0]     = l0;
    Xlo[base + p0 + 2] = l1;
}

// ---------------------------------------------------------------------------
// Layer-1 GEMM (fp32 input, converts + interleaves on stage). Split-K, 2 CTAs/SM.
// ---------------------------------------------------------------------------
__global__ __launch_bounds__(512, 2)
void gemm1_kernel(const float* __restrict__ xprev,
                  const uint2* __restrict__ Whi_g,
                  const uint2* __restrict__ Wlo_g,
                  float* __restrict__ tout)
{
    constexpr int NO = 128;
    constexpr int SA = 36;
    constexpr int WP2 = 132;
    constexpr int NT = 8;

    extern __shared__ uint32_t sm[];
    uint32_t* Ahi = sm;                       // [128][36] words, interleaved k2 order
    uint32_t* Alo = sm + 128 * SA;
    uint2* B2hi = (uint2*)(sm + 2 * 128 * SA);   // [32][132] uint2
    uint2* B2lo = B2hi + 32 * WP2;

    const int tid = threadIdx.x;
    const int wid = tid >> 5;
    const int l   = tid & 31;
    const int n0  = blockIdx.x * 128;

    constexpr int BW4 = 32 * WP2 / 2;         // uint4 count per plane
    const uint4* hs = (const uint4*)Whi_g;
    const uint4* ls = (const uint4*)Wlo_g;
    for (int i = tid; i < BW4; i += 512) {
        ((uint4*)B2hi)[i] = hs[i];
        ((uint4*)B2lo)[i] = ls[i];
    }

    const int rg = wid & 7;
    const int cg = wid >> 3;
    const int r0 = rg * 16;
    const int q   = l & 3;
    const int gid = l >> 2;
    const int cbase = cg * 64;
    const int hh = l >> 4;
    const int lh = l & 15;

    // interleaved store positions for staging (chunk-local 32 words)
    const int mm = lh & 3;
    const int sp0 = 8 * (lh >> 2) + 4 * (mm & 1) + (mm >> 1);

    float acc[NT][4];
#pragma unroll
    for (int nt = 0; nt < NT; nt++)
#pragma unroll
        for (int c = 0; c < 4; c++) acc[nt][c] = 0.f;

#pragma unroll
    for (int ck = 0; ck < 2; ck++) {
#pragma unroll
        for (int it = 0; it < 4; it++) {
            int mr = it * 32 + wid * 2 + hh;
            int node = n0 + mr;
            float4 xv = make_float4(0.f, 0.f, 0.f, 0.f);
            if (node < N_NODES)
                xv = *(const float4*)&xprev[(size_t)node * 128 + 64 * ck + 4 * lh];
            uint32_t h0 = cvt2(xv.x, xv.y), h1 = cvt2(xv.z, xv.w);
            uint32_t l0 = cvt2(xv.x - unlo(h0), xv.y - unhi(h0));
            uint32_t l1 = cvt2(xv.z - unlo(h1), xv.w - unhi(h1));
            Ahi[mr * SA + sp0]     = h0;
            Ahi[mr * SA + sp0 + 2] = h1;
            Alo[mr * SA + sp0]     = l0;
            Alo[mr * SA + sp0 + 2] = l1;
        }
        __syncthreads();

#pragma unroll
        for (int kc = 0; kc < 4; kc++) {
            const int wA = kc * 8 + 2 * q;
            uint2 ahA = *(const uint2*)&Ahi[(r0 + gid) * SA + wA];      // a0, a2
            uint2 ahB = *(const uint2*)&Ahi[(r0 + gid + 8) * SA + wA];  // a1, a3
            uint2 alA = *(const uint2*)&Alo[(r0 + gid) * SA + wA];
            uint2 alB = *(const uint2*)&Alo[(r0 + gid + 8) * SA + wA];
            const uint2* Bh = &B2hi[(ck * 16 + kc * 4 + q) * WP2 + cbase + gid];
            const uint2* Bl = &B2lo[(ck * 16 + kc * 4 + q) * WP2 + cbase + gid];
#pragma unroll
            for (int nt = 0; nt < NT; nt++) {
                uint2 bh = Bh[nt * 8];
                uint2 bl = Bl[nt * 8];
                MMA_BF16(acc[nt], ahA.x, ahB.x, ahA.y, ahB.y, bh.x, bh.y);
                MMA_BF16(acc[nt], alA.x, alB.x, alA.y, alB.y, bh.x, bh.y);
                MMA_BF16(acc[nt], ahA.x, ahB.x, ahA.y, ahB.y, bl.x, bl.y);
            }
        }
        __syncthreads();
    }

    const int row = n0 + r0 + gid;
#pragma unroll
    for (int nt = 0; nt < NT; nt++) {
        const int col = cbase + nt * 8 + q * 2;
        *(float2*)&tout[(size_t)row * NO + col]       = make_float2(acc[nt][0], acc[nt][1]);
        *(float2*)&tout[(size_t)(row + 8) * NO + col] = make_float2(acc[nt][2], acc[nt][3]);
    }
}

// ---------------------------------------------------------------------------
// X2 GEMM (layers 2/3): A pre-activated + pre-packed (interleaved) from gatherx.
// A-staging is a pure uint2 copy. All fragment loads are LDS.64. 2 CTAs/SM.
// ---------------------------------------------------------------------------
template <int NO>
__global__ __launch_bounds__(512, 2)
void gemm_x2_kernel(const uint32_t* __restrict__ Xhi_g,
                    const uint32_t* __restrict__ Xlo_g,
                    const uint2* __restrict__ Whi_g,
                    const uint2* __restrict__ Wlo_g,
                    float* __restrict__ tout)
{
    constexpr int SA = 36;
    constexpr int WP2 = (NO == 128) ? 132 : 68;
    constexpr int NT = NO / 16;

    extern __shared__ uint32_t sm[];
    uint32_t* Ahi = sm;
    uint32_t* Alo = sm + 128 * SA;
    uint2* B2hi = (uint2*)(sm + 2 * 128 * SA);
    uint2* B2lo = B2hi + 32 * WP2;

    const int tid = threadIdx.x;
    const int wid = tid >> 5;
    const int l   = tid & 31;
    const int n0  = blockIdx.x * 128;

    constexpr int BW4 = 32 * WP2 / 2;
    const uint4* hs = (const uint4*)Whi_g;
    const uint4* ls = (const uint4*)Wlo_g;
    for (int i = tid; i < BW4; i += 512) {
        ((uint4*)B2hi)[i] = hs[i];
        ((uint4*)B2lo)[i] = ls[i];
    }

    const int rg = wid & 7;
    const int cg = wid >> 3;
    const int r0 = rg * 16;
    const int q   = l & 3;
    const int gid = l >> 2;
    const int cbase = cg * (NO / 2);
    const int hh = l >> 4;
    const int lh = l & 15;

    float acc[NT][4];
#pragma unroll
    for (int nt = 0; nt < NT; nt++)
#pragma unroll
        for (int c = 0; c < 4; c++) acc[nt][c] = 0.f;

#pragma unroll
    for (int ck = 0; ck < 2; ck++) {
        // ---- stage A chunk: pure copy (order-oblivious) ----
#pragma unroll
        for (int it = 0; it < 4; it++) {
            int mr = it * 32 + wid * 2 + hh;
            size_t off = (size_t)(n0 + mr) * 64 + ck * 32 + 2 * lh;
            *(uint2*)&Ahi[mr * SA + 2 * lh] = *(const uint2*)&Xhi_g[off];
            *(uint2*)&Alo[mr * SA + 2 * lh] = *(const uint2*)&Xlo_g[off];
        }
        __syncthreads();

#pragma unroll
        for (int kc = 0; kc < 4; kc++) {
            const int wA = kc * 8 + 2 * q;
            uint2 ahA = *(const uint2*)&Ahi[(r0 + gid) * SA + wA];
            uint2 ahB = *(const uint2*)&Ahi[(r0 + gid + 8) * SA + wA];
            uint2 alA = *(const uint2*)&Alo[(r0 + gid) * SA + wA];
            uint2 alB = *(const uint2*)&Alo[(r0 + gid + 8) * SA + wA];
            const uint2* Bh = &B2hi[(ck * 16 + kc * 4 + q) * WP2 + cbase + gid];
            const uint2* Bl = &B2lo[(ck * 16 + kc * 4 + q) * WP2 + cbase + gid];
#pragma unroll
            for (int nt = 0; nt < NT; nt++) {
                uint2 bh = Bh[nt * 8];
                uint2 bl = Bl[nt * 8];
                MMA_BF16(acc[nt], ahA.x, ahB.x, ahA.y, ahB.y, bh.x, bh.y);
                MMA_BF16(acc[nt], alA.x, alB.x, alA.y, alB.y, bh.x, bh.y);
                MMA_BF16(acc[nt], ahA.x, ahB.x, ahA.y, ahB.y, bl.x, bl.y);
            }
        }
        __syncthreads();
    }

    const int row = n0 + r0 + gid;
#pragma unroll
    for (int nt = 0; nt < NT; nt++) {
        const int col = cbase + nt * 8 + q * 2;
        *(float2*)&tout[(size_t)row * NO + col]       = make_float2(acc[nt][0], acc[nt][1]);
        *(float2*)&tout[(size_t)(row + 8) * NO + col] = make_float2(acc[nt][2], acc[nt][3]);
    }
}

// ---------------------------------------------------------------------------
// Final: out = relu(t3 + gather(t3) + b3)   (d=64, 2 nodes/warp)
// ---------------------------------------------------------------------------
__global__ void epi_kernel(const float* __restrict__ t3,
                           const float* __restrict__ b3,
                           float* __restrict__ out)
{
    int warp = blockIdx.x * 8 + (threadIdx.x >> 5);
    int lane = threadIdx.x & 31;
    int node = warp * 2 + (lane >> 4);
    int l = lane & 15;
    if (node >= N_NODES) return;

    int deg = g_cursor[node];
    if (deg > CAP) deg = CAP;
    const int* sl = &g_slots[(size_t)node * CAP];
    const float* tb = t3 + 4 * l;

    float4 acc = make_float4(0.f, 0.f, 0.f, 0.f);
    int j = 0;
    for (; j + 7 < deg; j += 8) {
        float4 v0 = *(const float4*)&tb[(size_t)sl[j    ] * 64];
        float4 v1 = *(const float4*)&tb[(size_t)sl[j + 1] * 64];
        float4 v2 = *(const float4*)&tb[(size_t)sl[j + 2] * 64];
        float4 v3 = *(const float4*)&tb[(size_t)sl[j + 3] * 64];
        float4 v4 = *(const float4*)&tb[(size_t)sl[j + 4] * 64];
        float4 v5 = *(const float4*)&tb[(size_t)sl[j + 5] * 64];
        float4 v6 = *(const float4*)&tb[(size_t)sl[j + 6] * 64];
        float4 v7 = *(const float4*)&tb[(size_t)sl[j + 7] * 64];
        acc.x += (v0.x + v1.x) + (v2.x + v3.x) + (v4.x + v5.x) + (v6.x + v7.x);
        acc.y += (v0.y + v1.y) + (v2.y + v3.y) + (v4.y + v5.y) + (v6.y + v7.y);
        acc.z += (v0.z + v1.z) + (v2.z + v3.z) + (v4.z + v5.z) + (v6.z + v7.z);
        acc.w += (v0.w + v1.w) + (v2.w + v3.w) + (v4.w + v5.w) + (v6.w + v7.w);
    }
    for (; j + 3 < deg; j += 4) {
        float4 v0 = *(const float4*)&tb[(size_t)sl[j    ] * 64];
        float4 v1 = *(const float4*)&tb[(size_t)sl[j + 1] * 64];
        float4 v2 = *(const float4*)&tb[(size_t)sl[j + 2] * 64];
        float4 v3 = *(const float4*)&tb[(size_t)sl[j + 3] * 64];
        acc.x += (v0.x + v1.x) + (v2.x + v3.x);
        acc.y += (v0.y + v1.y) + (v2.y + v3.y);
        acc.z += (v0.z + v1.z) + (v2.z + v3.z);
        acc.w += (v0.w + v1.w) + (v2.w + v3.w);
    }
    for (; j < deg; j++) {
        float4 v = *(const float4*)&tb[(size_t)sl[j] * 64];
        acc.x += v.x; acc.y += v.y; acc.z += v.z; acc.w += v.w;
    }
    float4 tv = *(const float4*)&t3[(size_t)node * 64 + 4 * l];
    float4 bv = *(const float4*)&b3[4 * l];
    float4 o;
    o.x = fmaxf(tv.x + acc.x + bv.x, 0.f);
    o.y = fmaxf(tv.y + acc.y + bv.y, 0.f);
    o.z = fmaxf(tv.z + acc.z + bv.z, 0.f);
    o.w = fmaxf(tv.w + acc.w + bv.w, 0.f);
    *(float4*)&out[(size_t)node * 64 + 4 * l] = o;
}

extern "C" void kernel_launch(void* const* d_in, const int* in_sizes, int n_in,
                              void* d_out, int out_size)
{
    const float* in_feat = (const float*)d_in[0];
    const float* W1      = (const float*)d_in[1];
    const float* b1      = (const float*)d_in[2];
    const float* W2      = (const float*)d_in[3];
    const float* b2      = (const float*)d_in[4];
    const float* W3      = (const float*)d_in[5];
    const float* b3      = (const float*)d_in[6];
    const int*   src     = (const int*)d_in[7];
    const int*   dst     = (const int*)d_in[8];
    float* out = (float*)d_out;

    float* t;
    uint32_t *xhi, *xlo;
    uint2* wpre;
    int* cur;
    cudaGetSymbolAddress((void**)&t,    g_t);
    cudaGetSymbolAddress((void**)&xhi,  g_xhi);
    cudaGetSymbolAddress((void**)&xlo,  g_xlo);
    cudaGetSymbolAddress((void**)&wpre, g_Wpre2);
    cudaGetSymbolAddress((void**)&cur,  g_cursor);

    constexpr int SMEM_128 = 2 * 128 * 36 * 4 + 2 * 32 * 132 * 8;  // 104448
    constexpr int SMEM_64  = 2 * 128 * 36 * 4 + 2 * 32 * 68 * 8;   // 71680
    cudaFuncSetAttribute((const void*)gemm1_kernel,
                         cudaFuncAttributeMaxDynamicSharedMemorySize, SMEM_128);
    cudaFuncSetAttribute((const void*)gemm_x2_kernel<128>,
                         cudaFuncAttributeMaxDynamicSharedMemorySize, SMEM_128);
    cudaFuncSetAttribute((const void*)gemm_x2_kernel<64>,
                         cudaFuncAttributeMaxDynamicSharedMemorySize, SMEM_64);

    const int g128_blocks = (N_NODES + 7) / 8;   // 6250

    // Bucket build + W pre-split (single merged launch)
    cudaMemsetAsync(cur, 0, N_NODES * sizeof(int));
    build_kernel<<<FB + 3, 256>>>(src, dst, W1, W2, W3);

    // Layer 1: t = in_feat @ W1^T
    gemm1_kernel<<<NB, 512, SMEM_128>>>(in_feat, wpre + L1HI, wpre + L1LO, t);
    // X = pack(relu(t + gather(t) + b1))
    gatherx_kernel<<<g128_blocks, 256>>>(t, b1, xhi, xlo);

    // Layer 2: t = X @ W2^T
    gemm_x2_kernel<128><<<NB, 512, SMEM_128>>>(xhi, xlo, wpre + L2HI, wpre + L2LO, t);
    // X = pack(relu(t + gather(t) + b2))
    gatherx_kernel<<<g128_blocks, 256>>>(t, b2, xhi, xlo);

    // Layer 3: t(64-wide) = X @ W3^T
    gemm_x2_kernel<64><<<NB, 512, SMEM_64>>>(xhi, xlo, wpre + L3HI, wpre + L3LO, t);

    // Output: out = relu(t3 + gather(t3) + b3)
    epi_kernel<<<(N_NODES + 15) / 16, 256>>>(t, b3, out);
}